// round 1
// baseline (speedup 1.0000x reference)
#include <cuda_runtime.h>

// Performer FAVOR+ non-causal attention, fp32 SIMT baseline.
// b=8, h=16 -> BH=128;  n=4096, d=e=64, m=256.
//
// Phase 1 (kphase): per bh, stream k/v tiles; accumulate
//   U[m]   = sum_n exp(dash_k - diag_k)
//   C[m,e] = sum_n exp(dash_k - diag_k) * v[n,e]
//   vsum[e]= sum_n v[n,e],  stab = max(dash_k)   (lazy stabilizer)
// then k_sum = ratio*(e^-stab * U + eps*n),
//      context = ratio*(e^-stab * C + eps*vsum).
// Phase 2 (qphase): per 64-row q tile: dash, per-row max, q', then
//   denom = q'.k_sum and out = (q' @ context)/denom.

#define BHn 128
#define Nn  4096
#define Dn  64
#define Mn  256
#define TNn 64
#define NTILES (Nn / TNn)

#define NORMV 0.35355339059327378f   /* 64^-0.25 */
#define RATIO 0.0625f                /* 256^-0.5 */
#define EPSV  1e-4f

__device__ float g_ksum[BHn * Mn];          // 128 KB
__device__ float g_ctx[BHn * Mn * Dn];      // 8 MB

// ---------------------------------------------------------------------------
// Kernel 1: K phase. One CTA per bh, 256 threads.
// ---------------------------------------------------------------------------
__global__ __launch_bounds__(256, 1) void kphase_kernel(
    const float* __restrict__ kg, const float* __restrict__ vg,
    const float* __restrict__ projg) {
  extern __shared__ float sm1[];
  float* proj_s = sm1;                   // [64][256]   proj_s[kk*256+m]
  float* k_s    = proj_s + 64 * 256;     // [64][65]    k_s[kk*65+r] (normalized)
  float* v_s    = k_s + 64 * 65;         // [64][64]
  float* E_s    = v_s + 64 * 64;         // [64][256]
  float* diag_s = E_s + 64 * 256;        // [64]
  float* vsum_s = diag_s + 64;           // [64]
  float* red_s  = vsum_s + 64;           // [32]

  const int bh  = blockIdx.x;
  const int tid = threadIdx.x;
  const float* kb = kg + (size_t)bh * Nn * Dn;
  const float* vb = vg + (size_t)bh * Nn * Dn;

  for (int idx = tid; idx < Mn * Dn; idx += 256) {
    int m = idx >> 6, kk = idx & 63;
    proj_s[kk * Mn + m] = projg[idx];
  }

  // dash matmul mapping: warp rg owns rows r0..r0+7, lane group owns 8 m-cols
  const int rg = tid >> 5;
  const int r0 = rg * 8;
  const int m0 = (tid & 31) * 8;
  // C matmul mapping: 8 m-rows x 8 e-cols per thread
  const int tm0 = (tid >> 3) * 8;
  const int te0 = (tid & 7) * 8;

  float C[8][8];
#pragma unroll
  for (int i = 0; i < 8; i++)
#pragma unroll
    for (int j = 0; j < 8; j++) C[i][j] = 0.f;
  float U = 0.f, vsum = 0.f, dmax = -1e30f;

  __syncthreads();

  for (int t = 0; t < NTILES; t++) {
    const float* kt = kb + t * TNn * Dn;
    const float* vt = vb + t * TNn * Dn;
#pragma unroll
    for (int idx = tid; idx < TNn * Dn; idx += 256) {
      int r = idx >> 6, kk = idx & 63;
      k_s[kk * 65 + r] = kt[idx] * NORMV;
      v_s[idx] = vt[idx];
    }
    __syncthreads();

    if (tid < TNn) {
      float s = 0.f;
#pragma unroll
      for (int kk = 0; kk < Dn; kk++) { float x = k_s[kk * 65 + tid]; s += x * x; }
      diag_s[tid] = 0.5f * s;
      float vs = 0.f;
#pragma unroll
      for (int r = 0; r < TNn; r++) vs += v_s[r * Dn + tid];
      vsum += vs;
    }

    float dash[8][8];
#pragma unroll
    for (int i = 0; i < 8; i++)
#pragma unroll
      for (int j = 0; j < 8; j++) dash[i][j] = 0.f;

#pragma unroll 4
    for (int kk = 0; kk < Dn; kk++) {
      float a[8];
#pragma unroll
      for (int i = 0; i < 8; i++) a[i] = k_s[kk * 65 + r0 + i];
      float4 b0 = *(const float4*)&proj_s[kk * Mn + m0];
      float4 b1 = *(const float4*)&proj_s[kk * Mn + m0 + 4];
      float b[8] = {b0.x, b0.y, b0.z, b0.w, b1.x, b1.y, b1.z, b1.w};
#pragma unroll
      for (int i = 0; i < 8; i++)
#pragma unroll
        for (int j = 0; j < 8; j++) dash[i][j] += a[i] * b[j];
    }
    __syncthreads();  // diag_s ready

    // E = exp(dash - diag); track max(dash)
#pragma unroll
    for (int i = 0; i < 8; i++) {
      float dg = diag_s[r0 + i];
      float ev[8];
#pragma unroll
      for (int j = 0; j < 8; j++) {
        float dv = dash[i][j];
        dmax = fmaxf(dmax, dv);
        ev[j] = __expf(dv - dg);
      }
      *(float4*)&E_s[(r0 + i) * Mn + m0]     = make_float4(ev[0], ev[1], ev[2], ev[3]);
      *(float4*)&E_s[(r0 + i) * Mn + m0 + 4] = make_float4(ev[4], ev[5], ev[6], ev[7]);
    }
    __syncthreads();  // E_s ready

    // U[m] += column sums (thread owns column m = tid)
    {
      float u = 0.f;
#pragma unroll
      for (int r = 0; r < TNn; r++) u += E_s[r * Mn + tid];
      U += u;
    }
    // C += E^T @ V
#pragma unroll 4
    for (int r = 0; r < TNn; r++) {
      float4 a0 = *(const float4*)&E_s[r * Mn + tm0];
      float4 a1 = *(const float4*)&E_s[r * Mn + tm0 + 4];
      float4 b0 = *(const float4*)&v_s[r * Dn + te0];
      float4 b1 = *(const float4*)&v_s[r * Dn + te0 + 4];
      float a[8] = {a0.x, a0.y, a0.z, a0.w, a1.x, a1.y, a1.z, a1.w};
      float b[8] = {b0.x, b0.y, b0.z, b0.w, b1.x, b1.y, b1.z, b1.w};
#pragma unroll
      for (int i = 0; i < 8; i++)
#pragma unroll
        for (int j = 0; j < 8; j++) C[i][j] += a[i] * b[j];
    }
    __syncthreads();  // protect E_s / v_s / k_s before next tile load
  }

  // block max of dash
  float bm = dmax;
#pragma unroll
  for (int off = 16; off; off >>= 1)
    bm = fmaxf(bm, __shfl_xor_sync(0xffffffffu, bm, off));
  if ((tid & 31) == 0) red_s[tid >> 5] = bm;
  if (tid < TNn) vsum_s[tid] = vsum;
  __syncthreads();
  if (tid == 0) {
    float mm = red_s[0];
#pragma unroll
    for (int w = 1; w < 8; w++) mm = fmaxf(mm, red_s[w]);
    red_s[0] = mm;
  }
  __syncthreads();
  const float stab  = red_s[0];
  const float scale = __expf(-stab);

  g_ksum[bh * Mn + tid] = RATIO * (scale * U + EPSV * (float)Nn);

  float* ctxg = g_ctx + (size_t)bh * Mn * Dn;
#pragma unroll
  for (int i = 0; i < 8; i++) {
#pragma unroll
    for (int j = 0; j < 8; j++) {
      ctxg[(tm0 + i) * Dn + te0 + j] =
          RATIO * (scale * C[i][j] + EPSV * vsum_s[te0 + j]);
    }
  }
}

// ---------------------------------------------------------------------------
// Kernel 2: Q phase. grid (64 tiles, 128 bh), 256 threads.
// ---------------------------------------------------------------------------
__global__ __launch_bounds__(256, 1) void qphase_kernel(
    const float* __restrict__ qg, const float* __restrict__ projg,
    float* __restrict__ outg) {
  extern __shared__ float sm2[];
  float* proj_s  = sm2;                  // [64][256]
  float* q_s     = proj_s + 64 * 256;    // [64][65]
  float* ctx_s   = q_s + 64 * 65;        // [256][64]
  float* qT      = ctx_s + 256 * 64;     // [256][68]  q' transposed (m-major)
  float* ksum_s  = qT + 256 * 68;        // [256]
  float* diag_s  = ksum_s + 256;         // [64]
  float* denom_s = diag_s + 64;          // [64]

  const int bh   = blockIdx.y;
  const int tile = blockIdx.x;
  const int tid  = threadIdx.x;
  const float* qt   = qg + ((size_t)bh * Nn + (size_t)tile * TNn) * Dn;
  const float* ctxg = g_ctx + (size_t)bh * Mn * Dn;

  for (int idx = tid; idx < Mn * Dn; idx += 256) {
    int m = idx >> 6, kk = idx & 63;
    proj_s[kk * Mn + m] = projg[idx];
    ctx_s[idx] = ctxg[idx];
  }
  ksum_s[tid] = g_ksum[bh * Mn + tid];
#pragma unroll
  for (int idx = tid; idx < TNn * Dn; idx += 256) {
    int r = idx >> 6, kk = idx & 63;
    q_s[kk * 65 + r] = qt[idx] * NORMV;
  }
  __syncthreads();

  if (tid < TNn) {
    float s = 0.f;
#pragma unroll
    for (int kk = 0; kk < Dn; kk++) { float x = q_s[kk * 65 + tid]; s += x * x; }
    diag_s[tid] = 0.5f * s;
  }

  const int rg = tid >> 5;
  const int r0 = rg * 8;
  const int m0 = (tid & 31) * 8;

  float dash[8][8];
#pragma unroll
  for (int i = 0; i < 8; i++)
#pragma unroll
    for (int j = 0; j < 8; j++) dash[i][j] = 0.f;

#pragma unroll 4
  for (int kk = 0; kk < Dn; kk++) {
    float a[8];
#pragma unroll
    for (int i = 0; i < 8; i++) a[i] = q_s[kk * 65 + r0 + i];
    float4 b0 = *(const float4*)&proj_s[kk * Mn + m0];
    float4 b1 = *(const float4*)&proj_s[kk * Mn + m0 + 4];
    float b[8] = {b0.x, b0.y, b0.z, b0.w, b1.x, b1.y, b1.z, b1.w};
#pragma unroll
    for (int i = 0; i < 8; i++)
#pragma unroll
      for (int j = 0; j < 8; j++) dash[i][j] += a[i] * b[j];
  }
  __syncthreads();  // diag_s ready

  // Row max (warp rg fully owns rows r0..r0+7), then q' and denom partials.
#pragma unroll
  for (int i = 0; i < 8; i++) {
    float mx = dash[i][0];
#pragma unroll
    for (int j = 1; j < 8; j++) mx = fmaxf(mx, dash[i][j]);
#pragma unroll
    for (int off = 16; off; off >>= 1)
      mx = fmaxf(mx, __shfl_xor_sync(0xffffffffu, mx, off));
    const float sub = diag_s[r0 + i] + mx;
    float dsum = 0.f;
#pragma unroll
    for (int j = 0; j < 8; j++) {
      float qp = RATIO * (__expf(dash[i][j] - sub) + EPSV);
      dsum += qp * ksum_s[m0 + j];
      qT[(m0 + j) * 68 + r0 + i] = qp;
    }
#pragma unroll
    for (int off = 16; off; off >>= 1)
      dsum += __shfl_xor_sync(0xffffffffu, dsum, off);
    if ((tid & 31) == 0) denom_s[r0 + i] = dsum;
  }
  __syncthreads();  // qT, denom ready

  // out[r][e] = (sum_m q'[r][m] * ctx[m][e]) / denom[r]
  const int r1 = (tid >> 4) * 4;
  const int e0 = (tid & 15) * 4;
  float acc[4][4];
#pragma unroll
  for (int i = 0; i < 4; i++)
#pragma unroll
    for (int j = 0; j < 4; j++) acc[i][j] = 0.f;

#pragma unroll 4
  for (int m = 0; m < Mn; m++) {
    float4 a4 = *(const float4*)&qT[m * 68 + r1];
    float4 b4 = *(const float4*)&ctx_s[m * Dn + e0];
    float a[4] = {a4.x, a4.y, a4.z, a4.w};
    float b[4] = {b4.x, b4.y, b4.z, b4.w};
#pragma unroll
    for (int i = 0; i < 4; i++)
#pragma unroll
      for (int j = 0; j < 4; j++) acc[i][j] += a[i] * b[j];
  }

  float* ob = outg + ((size_t)bh * Nn + (size_t)tile * TNn) * Dn;
#pragma unroll
  for (int i = 0; i < 4; i++) {
    float inv = 1.f / denom_s[r1 + i];
    *(float4*)&ob[(r1 + i) * Dn + e0] =
        make_float4(acc[i][0] * inv, acc[i][1] * inv,
                    acc[i][2] * inv, acc[i][3] * inv);
  }
}

// ---------------------------------------------------------------------------
extern "C" void kernel_launch(void* const* d_in, const int* in_sizes, int n_in,
                              void* d_out, int out_size) {
  const float* q    = (const float*)d_in[0];
  const float* k    = (const float*)d_in[1];
  const float* v    = (const float*)d_in[2];
  const float* proj = (const float*)d_in[3];
  float* out = (float*)d_out;

  const int smem1 = (64 * 256 + 64 * 65 + 64 * 64 + 64 * 256 + 64 + 64 + 32) * 4;
  const int smem2 = (64 * 256 + 64 * 65 + 256 * 64 + 256 * 68 + 256 + 64 + 64) * 4;

  cudaFuncSetAttribute(kphase_kernel, cudaFuncAttributeMaxDynamicSharedMemorySize, smem1);
  cudaFuncSetAttribute(qphase_kernel, cudaFuncAttributeMaxDynamicSharedMemorySize, smem2);

  kphase_kernel<<<BHn, 256, smem1>>>(k, v, proj);
  qphase_kernel<<<dim3(NTILES, BHn), 256, smem2>>>(q, proj, out);
}

// round 3
// speedup vs baseline: 1.2361x; 1.2361x over previous
#include <cuda_runtime.h>

// Performer FAVOR+ non-causal attention — fp32 SIMT v2.
// Changes vs v1: pre-transposed proj in global (g_projT), no in-CTA
// transposes, row-major q' (no 32-way-conflict qT), vectorized broadcast
// A-loads, packed fma.rn.f32x2 (FFMA2) everywhere.

#define BHn 128
#define Nn  4096
#define Dn  64
#define Mn  256
#define TNn 64
#define NTILES (Nn / TNn)

#define NORMV 0.35355339059327378f   /* 64^-0.25 */
#define RATIO 0.0625f                /* 256^-0.5 */
#define EPSV  1e-4f

typedef unsigned long long u64t;

__device__ float g_projT[Dn * Mn];        // [kk][m]
__device__ float g_ksum[BHn * Mn];
__device__ float g_ctx[BHn * Mn * Dn];    // [bh][m][e]

#define FFMA2(acc, a, b) asm("fma.rn.f32x2 %0, %1, %2, %0;" : "+l"(acc) : "l"(a), "l"(b))
#define ADDF2(acc, b)    asm("add.rn.f32x2 %0, %0, %1;" : "+l"(acc) : "l"(b))
#define DUP2(d, x)       asm("mov.b64 %0, {%1, %1};" : "=l"(d) : "f"(x))
#define UNPK2(lo, hi, p) asm("mov.b64 {%0, %1}, %2;" : "=f"(lo), "=f"(hi) : "l"(p))

__device__ __forceinline__ float f4c(const float4& v, int u) {
  return (u == 0) ? v.x : (u == 1) ? v.y : (u == 2) ? v.z : v.w;
}

// ---------------------------------------------------------------------------
// Kernel 0: transpose proj [m][kk] -> g_projT [kk][m]  (one-time per replay)
// ---------------------------------------------------------------------------
__global__ void transpose_proj_kernel(const float* __restrict__ p) {
  int idx = blockIdx.x * 256 + threadIdx.x;   // 16384 elements
  int m = idx >> 6, kk = idx & 63;
  g_projT[kk * Mn + m] = p[idx];
}

// ---------------------------------------------------------------------------
// Kernel 1: K phase. One CTA per bh, 256 threads.
// ---------------------------------------------------------------------------
__global__ __launch_bounds__(256, 1) void kphase_kernel(
    const float* __restrict__ kg, const float* __restrict__ vg) {
  extern __shared__ float sm[];
  float* proj_s = sm;                 // [64][256]  kk-major
  float* k_s    = proj_s + 16384;     // [64][64]   row-major, pre-scaled
  float* v_s    = k_s + 4096;         // [64][64]
  float* E_s    = v_s + 4096;         // [64][256]  row-major
  float* Ured   = E_s + 16384;        // [8][256]
  float* vsum_s = Ured + 2048;        // [64]
  float* red_s  = vsum_s + 64;        // [32]

  const int bh  = blockIdx.x;
  const int tid = threadIdx.x;
  const int lane = tid & 31;
  const int wid  = tid >> 5;
  const int r0 = wid * 8;             // dash: rows
  const int m0 = lane * 8;            // dash: m cols
  const int tm0 = (tid >> 3) * 8;     // C: m rows
  const int te0 = (tid & 7) * 8;      // C: e cols

  const float4* kb4 = (const float4*)(kg + (size_t)bh * Nn * Dn);
  const float4* vb4 = (const float4*)(vg + (size_t)bh * Nn * Dn);

  {
    const float4* pT = (const float4*)g_projT;
    float4* ps4 = (float4*)proj_s;
    for (int i = tid; i < 4096; i += 256) ps4[i] = pT[i];
  }

  u64t C2[8][4];
#pragma unroll
  for (int i = 0; i < 8; i++)
#pragma unroll
    for (int j = 0; j < 4; j++) C2[i][j] = 0ull;
  float uacc[8] = {0.f, 0.f, 0.f, 0.f, 0.f, 0.f, 0.f, 0.f};
  u64t vs2[4] = {0ull, 0ull, 0ull, 0ull};
  float dmax = -1e30f;

  __syncthreads();

  for (int t = 0; t < NTILES; t++) {
    {
      float4* k4 = (float4*)k_s;
      float4* v4 = (float4*)v_s;
      for (int i = tid; i < 1024; i += 256) {
        float4 kv = kb4[t * 1024 + i];
        kv.x *= NORMV; kv.y *= NORMV; kv.z *= NORMV; kv.w *= NORMV;
        k4[i] = kv;
        v4[i] = vb4[t * 1024 + i];
      }
    }
    __syncthreads();

    // diag for this warp's 8 rows (all lanes end with the value)
    float dg[8];
#pragma unroll
    for (int i = 0; i < 8; i++) {
      float2 tv = *(const float2*)&k_s[(r0 + i) * 64 + lane * 2];
      float s = tv.x * tv.x + tv.y * tv.y;
#pragma unroll
      for (int off = 16; off; off >>= 1) s += __shfl_xor_sync(0xffffffffu, s, off);
      dg[i] = 0.5f * s;
    }

    // dash = k_s @ proj  (8 rows x 8 m per thread, FFMA2)
    u64t dacc[8][4];
#pragma unroll
    for (int i = 0; i < 8; i++)
#pragma unroll
      for (int j = 0; j < 4; j++) dacc[i][j] = 0ull;

#pragma unroll 2
    for (int kk4 = 0; kk4 < 16; kk4++) {
      float4 a[8];
#pragma unroll
      for (int i = 0; i < 8; i++)
        a[i] = *(const float4*)&k_s[(r0 + i) * 64 + kk4 * 4];
#pragma unroll
      for (int u = 0; u < 4; u++) {
        const ulonglong2* bp =
            (const ulonglong2*)&proj_s[(kk4 * 4 + u) * Mn + m0];
        ulonglong2 p0 = bp[0], p1 = bp[1];
#pragma unroll
        for (int i = 0; i < 8; i++) {
          u64t ad; DUP2(ad, f4c(a[i], u));
          FFMA2(dacc[i][0], ad, p0.x);
          FFMA2(dacc[i][1], ad, p0.y);
          FFMA2(dacc[i][2], ad, p1.x);
          FFMA2(dacc[i][3], ad, p1.y);
        }
      }
    }

    // E = exp(dash - diag); track max(dash); accumulate column partials
#pragma unroll
    for (int i = 0; i < 8; i++) {
      float d[8];
      UNPK2(d[0], d[1], dacc[i][0]);
      UNPK2(d[2], d[3], dacc[i][1]);
      UNPK2(d[4], d[5], dacc[i][2]);
      UNPK2(d[6], d[7], dacc[i][3]);
      float ev[8];
#pragma unroll
      for (int j = 0; j < 8; j++) {
        dmax = fmaxf(dmax, d[j]);
        ev[j] = __expf(d[j] - dg[i]);
        uacc[j] += ev[j];
      }
      *(float4*)&E_s[(r0 + i) * Mn + m0]     = make_float4(ev[0], ev[1], ev[2], ev[3]);
      *(float4*)&E_s[(r0 + i) * Mn + m0 + 4] = make_float4(ev[4], ev[5], ev[6], ev[7]);
    }
    __syncthreads();

    // C += E^T @ V  (8 m x 8 e per thread); vsum folded in (threads tm0==0)
#pragma unroll 4
    for (int r = 0; r < 64; r++) {
      float4 a0 = *(const float4*)&E_s[r * Mn + tm0];
      float4 a1 = *(const float4*)&E_s[r * Mn + tm0 + 4];
      ulonglong2 q0 = *(const ulonglong2*)&v_s[r * 64 + te0];
      ulonglong2 q1 = *(const ulonglong2*)&v_s[r * 64 + te0 + 4];
      if (tm0 == 0) {
        ADDF2(vs2[0], q0.x); ADDF2(vs2[1], q0.y);
        ADDF2(vs2[2], q1.x); ADDF2(vs2[3], q1.y);
      }
      float aa[8] = {a0.x, a0.y, a0.z, a0.w, a1.x, a1.y, a1.z, a1.w};
#pragma unroll
      for (int i = 0; i < 8; i++) {
        u64t ad; DUP2(ad, aa[i]);
        FFMA2(C2[i][0], ad, q0.x);
        FFMA2(C2[i][1], ad, q0.y);
        FFMA2(C2[i][2], ad, q1.x);
        FFMA2(C2[i][3], ad, q1.y);
      }
    }
    __syncthreads();
  }

  // ---- finalize ----
  float bm = dmax;
#pragma unroll
  for (int off = 16; off; off >>= 1)
    bm = fmaxf(bm, __shfl_xor_sync(0xffffffffu, bm, off));
  if (lane == 0) red_s[wid] = bm;

  *(float4*)&Ured[wid * 256 + m0]     = make_float4(uacc[0], uacc[1], uacc[2], uacc[3]);
  *(float4*)&Ured[wid * 256 + m0 + 4] = make_float4(uacc[4], uacc[5], uacc[6], uacc[7]);

  if (tid < 8) {
    float x0, x1, x2, x3, x4, x5, x6, x7;
    UNPK2(x0, x1, vs2[0]); UNPK2(x2, x3, vs2[1]);
    UNPK2(x4, x5, vs2[2]); UNPK2(x6, x7, vs2[3]);
    vsum_s[te0 + 0] = x0; vsum_s[te0 + 1] = x1;
    vsum_s[te0 + 2] = x2; vsum_s[te0 + 3] = x3;
    vsum_s[te0 + 4] = x4; vsum_s[te0 + 5] = x5;
    vsum_s[te0 + 6] = x6; vsum_s[te0 + 7] = x7;
  }
  __syncthreads();
  if (tid == 0) {
    float mm = red_s[0];
#pragma unroll
    for (int w = 1; w < 8; w++) mm = fmaxf(mm, red_s[w]);
    red_s[0] = mm;
  }
  __syncthreads();
  const float scale = __expf(-red_s[0]);

  float U = 0.f;
#pragma unroll
  for (int w = 0; w < 8; w++) U += Ured[w * 256 + tid];
  g_ksum[bh * Mn + tid] = RATIO * (scale * U + EPSV * (float)Nn);

  float* ctxg = g_ctx + (size_t)bh * Mn * Dn;
#pragma unroll
  for (int i = 0; i < 8; i++) {
    float c[8];
    UNPK2(c[0], c[1], C2[i][0]);
    UNPK2(c[2], c[3], C2[i][1]);
    UNPK2(c[4], c[5], C2[i][2]);
    UNPK2(c[6], c[7], C2[i][3]);
#pragma unroll
    for (int j = 0; j < 8; j++)
      c[j] = RATIO * (scale * c[j] + EPSV * vsum_s[te0 + j]);
    *(float4*)&ctxg[(tm0 + i) * Dn + te0]     = make_float4(c[0], c[1], c[2], c[3]);
    *(float4*)&ctxg[(tm0 + i) * Dn + te0 + 4] = make_float4(c[4], c[5], c[6], c[7]);
  }
}

// ---------------------------------------------------------------------------
// Kernel 2: Q phase. grid (64 tiles, 128 bh), 256 threads.
// ---------------------------------------------------------------------------
__global__ __launch_bounds__(256, 1) void qphase_kernel(
    const float* __restrict__ qg, float* __restrict__ outg) {
  extern __shared__ float sm[];
  float* bufA   = sm;                 // [64][256] proj, later [256][64] ctx
  float* q_s    = bufA + 16384;       // [64][64] row-major, pre-scaled
  float* qp_s   = q_s + 4096;         // [64][256] q' row-major
  float* ksum_s = qp_s + 16384;       // [256]
  float* denom_s = ksum_s + 256;      // [64]

  const int bh   = blockIdx.y;
  const int tile = blockIdx.x;
  const int tid  = threadIdx.x;
  const int lane = tid & 31;
  const int wid  = tid >> 5;
  const int r0 = wid * 8;
  const int m0 = lane * 8;

  const float4* qt4 =
      (const float4*)(qg + ((size_t)bh * Nn + (size_t)tile * TNn) * Dn);

  {
    const float4* pT = (const float4*)g_projT;
    float4* bA4 = (float4*)bufA;
    for (int i = tid; i < 4096; i += 256) bA4[i] = pT[i];
    float4* q4 = (float4*)q_s;
    for (int i = tid; i < 1024; i += 256) {
      float4 qv = qt4[i];
      qv.x *= NORMV; qv.y *= NORMV; qv.z *= NORMV; qv.w *= NORMV;
      q4[i] = qv;
    }
  }
  ksum_s[tid] = g_ksum[bh * Mn + tid];
  __syncthreads();

  // diag (warp-local)
  float dg[8];
#pragma unroll
  for (int i = 0; i < 8; i++) {
    float2 tv = *(const float2*)&q_s[(r0 + i) * 64 + lane * 2];
    float s = tv.x * tv.x + tv.y * tv.y;
#pragma unroll
    for (int off = 16; off; off >>= 1) s += __shfl_xor_sync(0xffffffffu, s, off);
    dg[i] = 0.5f * s;
  }

  // dash = q_s @ proj
  u64t dacc[8][4];
#pragma unroll
  for (int i = 0; i < 8; i++)
#pragma unroll
    for (int j = 0; j < 4; j++) dacc[i][j] = 0ull;

#pragma unroll 2
  for (int kk4 = 0; kk4 < 16; kk4++) {
    float4 a[8];
#pragma unroll
    for (int i = 0; i < 8; i++)
      a[i] = *(const float4*)&q_s[(r0 + i) * 64 + kk4 * 4];
#pragma unroll
    for (int u = 0; u < 4; u++) {
      const ulonglong2* bp = (const ulonglong2*)&bufA[(kk4 * 4 + u) * Mn + m0];
      ulonglong2 p0 = bp[0], p1 = bp[1];
#pragma unroll
      for (int i = 0; i < 8; i++) {
        u64t ad; DUP2(ad, f4c(a[i], u));
        FFMA2(dacc[i][0], ad, p0.x);
        FFMA2(dacc[i][1], ad, p0.y);
        FFMA2(dacc[i][2], ad, p1.x);
        FFMA2(dacc[i][3], ad, p1.y);
      }
    }
  }

  // epilogue: per-row max, q', denom; all intra-warp
  float ks[8];
#pragma unroll
  for (int j = 0; j < 8; j++) ks[j] = ksum_s[m0 + j];
#pragma unroll
  for (int i = 0; i < 8; i++) {
    float d[8];
    UNPK2(d[0], d[1], dacc[i][0]);
    UNPK2(d[2], d[3], dacc[i][1]);
    UNPK2(d[4], d[5], dacc[i][2]);
    UNPK2(d[6], d[7], dacc[i][3]);
    float mx = d[0];
#pragma unroll
    for (int j = 1; j < 8; j++) mx = fmaxf(mx, d[j]);
#pragma unroll
    for (int off = 16; off; off >>= 1)
      mx = fmaxf(mx, __shfl_xor_sync(0xffffffffu, mx, off));
    const float sub = dg[i] + mx;
    float qp[8];
    float dsum = 0.f;
#pragma unroll
    for (int j = 0; j < 8; j++) {
      qp[j] = RATIO * (__expf(d[j] - sub) + EPSV);
      dsum += qp[j] * ks[j];
    }
#pragma unroll
    for (int off = 16; off; off >>= 1)
      dsum += __shfl_xor_sync(0xffffffffu, dsum, off);
    if (lane == 0) denom_s[r0 + i] = dsum;
    *(float4*)&qp_s[(r0 + i) * Mn + m0]     = make_float4(qp[0], qp[1], qp[2], qp[3]);
    *(float4*)&qp_s[(r0 + i) * Mn + m0 + 4] = make_float4(qp[4], qp[5], qp[6], qp[7]);
  }
  __syncthreads();

  // overlay ctx into bufA
  {
    const float4* cg = (const float4*)(g_ctx + (size_t)bh * Mn * Dn);
    float4* bA4 = (float4*)bufA;
    for (int i = tid; i < 4096; i += 256) bA4[i] = cg[i];
  }
  __syncthreads();

  // out = (q' @ ctx) / denom   (4 rows x 4 e per thread)
  const int r1 = (tid >> 4) * 4;
  const int e0 = (tid & 15) * 4;
  u64t oacc[4][2];
#pragma unroll
  for (int i = 0; i < 4; i++) { oacc[i][0] = 0ull; oacc[i][1] = 0ull; }

#pragma unroll 2
  for (int m4 = 0; m4 < 64; m4++) {
    float4 a[4];
#pragma unroll
    for (int i = 0; i < 4; i++)
      a[i] = *(const float4*)&qp_s[(r1 + i) * Mn + m4 * 4];
#pragma unroll
    for (int u = 0; u < 4; u++) {
      ulonglong2 b = *(const ulonglong2*)&bufA[(m4 * 4 + u) * 64 + e0];
#pragma unroll
      for (int i = 0; i < 4; i++) {
        u64t ad; DUP2(ad, f4c(a[i], u));
        FFMA2(oacc[i][0], ad, b.x);
        FFMA2(oacc[i][1], ad, b.y);
      }
    }
  }

  float* ob = outg + ((size_t)bh * Nn + (size_t)tile * TNn) * Dn;
#pragma unroll
  for (int i = 0; i < 4; i++) {
    float inv = 1.f / denom_s[r1 + i];
    float o0, o1, o2, o3;
    UNPK2(o0, o1, oacc[i][0]);
    UNPK2(o2, o3, oacc[i][1]);
    *(float4*)&ob[(r1 + i) * 64 + e0] =
        make_float4(o0 * inv, o1 * inv, o2 * inv, o3 * inv);
  }
}

// ---------------------------------------------------------------------------
extern "C" void kernel_launch(void* const* d_in, const int* in_sizes, int n_in,
                              void* d_out, int out_size) {
  const float* q    = (const float*)d_in[0];
  const float* k    = (const float*)d_in[1];
  const float* v    = (const float*)d_in[2];
  const float* proj = (const float*)d_in[3];
  float* out = (float*)d_out;

  const int smem1 = (16384 + 4096 + 4096 + 16384 + 2048 + 64 + 32) * 4;
  const int smem2 = (16384 + 4096 + 16384 + 256 + 64) * 4;

  cudaFuncSetAttribute(kphase_kernel, cudaFuncAttributeMaxDynamicSharedMemorySize, smem1);
  cudaFuncSetAttribute(qphase_kernel, cudaFuncAttributeMaxDynamicSharedMemorySize, smem2);

  transpose_proj_kernel<<<64, 256>>>(proj);
  kphase_kernel<<<BHn, 256, smem1>>>(k, v);
  qphase_kernel<<<dim3(NTILES, BHn), 256, smem2>>>(q, out);
}